// round 4
// baseline (speedup 1.0000x reference)
#include <cuda_runtime.h>
#include <cuda_bf16.h>
#include <cstdint>

#define N_NODES 100000
#define C1 256
#define K_DIM 768
#define N_GRAPHS 512
#define MAX_EDGES 1600000

// ---- scratch (no allocations allowed) ----
__device__ float g_dinv[N_NODES];
__device__ __nv_bfloat16 g_h1b[(size_t)N_NODES * C1];   // x @ W1 (bf16 storage)
__device__ float g_h2[N_NODES * 2];
__device__ float g_gsum[N_GRAPHS * 2];
__device__ float g_gcnt[N_GRAPHS];
// CSR build
__device__ int g_cnt[N_NODES];
__device__ int g_cur[N_NODES];
__device__ int g_off[N_NODES + 1];
__device__ int g_csr[MAX_EDGES];
__device__ int g_bsum[128];
__device__ int g_boff[128];

// ---------------------------------------------------------------------------
__global__ void k_init(int N) {
    int i = blockIdx.x * blockDim.x + threadIdx.x;
    if (i < N) { g_cnt[i] = 0; g_cur[i] = 0; }
    if (i < N_GRAPHS * 2) g_gsum[i] = 0.0f;
    if (i < N_GRAPHS) g_gcnt[i] = 0.0f;
}

__global__ void k_hist(const int* __restrict__ dst, int E) {
    int e = blockIdx.x * blockDim.x + threadIdx.x;
    if (e < E) atomicAdd(&g_cnt[dst[e]], 1);
}

__global__ void k_dinv(int N) {
    int i = blockIdx.x * blockDim.x + threadIdx.x;
    if (i < N) g_dinv[i] = rsqrtf((float)g_cnt[i] + 1.0f);
}

// ---- two-level exclusive scan of g_cnt -> g_off ----------------------------
__global__ void k_bsum(int N) {
    __shared__ int sm[256];
    int b = blockIdx.x, t = threadIdx.x;
    int base = b * 1024 + t * 4;
    int s = 0;
#pragma unroll
    for (int j = 0; j < 4; j++) {
        int idx = base + j;
        if (idx < N) s += g_cnt[idx];
    }
    sm[t] = s;
    __syncthreads();
    for (int o = 128; o; o >>= 1) {
        if (t < o) sm[t] += sm[t + o];
        __syncthreads();
    }
    if (t == 0) g_bsum[b] = sm[0];
}

__global__ void k_top(int NB, int N) {
    if (threadIdx.x == 0 && blockIdx.x == 0) {
        int run = 0;
        for (int i = 0; i < NB; i++) { g_boff[i] = run; run += g_bsum[i]; }
        g_off[N] = run;
    }
}

__global__ void k_scan(int N) {
    __shared__ int warp_tot[8];
    int b = blockIdx.x, t = threadIdx.x;
    int lane = t & 31, wid = t >> 5;
    int base = b * 1024 + t * 4;
    int v[4];
#pragma unroll
    for (int j = 0; j < 4; j++) {
        int idx = base + j;
        v[j] = (idx < N) ? g_cnt[idx] : 0;
    }
    int tsum = v[0] + v[1] + v[2] + v[3];
    int incl = tsum;
#pragma unroll
    for (int o = 1; o < 32; o <<= 1) {
        int n = __shfl_up_sync(0xFFFFFFFFu, incl, o);
        if (lane >= o) incl += n;
    }
    if (lane == 31) warp_tot[wid] = incl;
    __syncthreads();
    if (wid == 0 && lane < 8) {
        int w = warp_tot[lane];
        int wi = w;
#pragma unroll
        for (int o = 1; o < 8; o <<= 1) {
            int n = __shfl_up_sync(0xFFu, wi, o);
            if (lane >= o) wi += n;
        }
        warp_tot[lane] = wi - w;
    }
    __syncthreads();
    int run = warp_tot[wid] + (incl - tsum) + g_boff[b];
#pragma unroll
    for (int j = 0; j < 4; j++) {
        int idx = base + j;
        if (idx < N) g_off[idx] = run;
        run += v[j];
    }
}

__global__ void k_place(const int* __restrict__ src, const int* __restrict__ dst, int E) {
    int e = blockIdx.x * blockDim.x + threadIdx.x;
    if (e >= E) return;
    int d = dst[e];
    int pos = g_off[d] + atomicAdd(&g_cur[d], 1);
    g_csr[pos] = src[e];
}

// ---------------------------------------------------------------------------
// TF32 tensor-core GEMM: h1 = X[M,768] @ W1[768,256], bf16 output.
// 512 threads (4x4 warps), BM=128, BN=256 (full C1 => X read ONCE), BK=16.
#define BM 128
#define BN 256
#define BK 16

__global__ __launch_bounds__(512, 1)
void k_gemm1(const float* __restrict__ X, const float* __restrict__ W, int M) {
    __shared__ float As[2][BM][BK + 4];     // 20.5 KB
    __shared__ float Bs[2][BK][BN + 4];     // 33.3 KB

    const int tid  = threadIdx.x;
    const int lane = tid & 31;
    const int warp = tid >> 5;
    const int wm = warp & 3;          // 0..3 -> M offset wm*32
    const int wn = warp >> 2;         // 0..3 -> N offset wn*64
    const int bm = blockIdx.x * BM;

    float acc[2][8][4];
#pragma unroll
    for (int i = 0; i < 2; i++)
#pragma unroll
        for (int j = 0; j < 8; j++)
#pragma unroll
            for (int t = 0; t < 4; t++) acc[i][j][t] = 0.0f;

    const int NS = K_DIM / BK;  // 48

    auto load_stage = [&](int s, int buf) {
        int k0 = s * BK;
        // A tile: 128x16 = 512 float4, 1 per thread
        {
            int row = tid >> 2;
            int ch  = tid & 3;
            int gr  = bm + row;
            int sz  = (gr < M) ? 16 : 0;
            if (gr >= M) gr = M - 1;
            const float* srcp = X + (size_t)gr * K_DIM + k0 + ch * 4;
            uint32_t dstp = (uint32_t)__cvta_generic_to_shared(&As[buf][row][ch * 4]);
            asm volatile("cp.async.cg.shared.global [%0], [%1], 16, %2;\n"
                         :: "r"(dstp), "l"(srcp), "r"(sz));
        }
        // B tile: 16x256 = 1024 float4, 2 per thread
#pragma unroll
        for (int l = 0; l < 2; l++) {
            int idx = tid + l * 512;
            int row = idx >> 6;
            int ch  = idx & 63;
            const float* srcp = W + (size_t)(k0 + row) * C1 + ch * 4;
            uint32_t dstp = (uint32_t)__cvta_generic_to_shared(&Bs[buf][row][ch * 4]);
            asm volatile("cp.async.cg.shared.global [%0], [%1], 16;\n"
                         :: "r"(dstp), "l"(srcp));
        }
        asm volatile("cp.async.commit_group;\n");
    };

    load_stage(0, 0);

    for (int s = 0; s < NS; s++) {
        int buf = s & 1;
        if (s + 1 < NS) {
            load_stage(s + 1, (s + 1) & 1);
            asm volatile("cp.async.wait_group 1;\n");
        } else {
            asm volatile("cp.async.wait_group 0;\n");
        }
        __syncthreads();

#pragma unroll
        for (int kk = 0; kk < 2; kk++) {
            uint32_t a[2][4], b[8][2];
#pragma unroll
            for (int i = 0; i < 2; i++) {
                int r = wm * 32 + i * 16 + (lane >> 2);
                int c = kk * 8 + (lane & 3);
                asm("cvt.rna.tf32.f32 %0, %1;" : "=r"(a[i][0]) : "f"(As[buf][r][c]));
                asm("cvt.rna.tf32.f32 %0, %1;" : "=r"(a[i][1]) : "f"(As[buf][r + 8][c]));
                asm("cvt.rna.tf32.f32 %0, %1;" : "=r"(a[i][2]) : "f"(As[buf][r][c + 4]));
                asm("cvt.rna.tf32.f32 %0, %1;" : "=r"(a[i][3]) : "f"(As[buf][r + 8][c + 4]));
            }
#pragma unroll
            for (int j = 0; j < 8; j++) {
                int rb = kk * 8 + (lane & 3);
                int cb = wn * 64 + j * 8 + (lane >> 2);
                asm("cvt.rna.tf32.f32 %0, %1;" : "=r"(b[j][0]) : "f"(Bs[buf][rb][cb]));
                asm("cvt.rna.tf32.f32 %0, %1;" : "=r"(b[j][1]) : "f"(Bs[buf][rb + 4][cb]));
            }
#pragma unroll
            for (int i = 0; i < 2; i++)
#pragma unroll
                for (int j = 0; j < 8; j++)
                    asm volatile(
                        "mma.sync.aligned.m16n8k8.row.col.f32.tf32.tf32.f32 "
                        "{%0,%1,%2,%3}, {%4,%5,%6,%7}, {%8,%9}, {%0,%1,%2,%3};\n"
                        : "+f"(acc[i][j][0]), "+f"(acc[i][j][1]),
                          "+f"(acc[i][j][2]), "+f"(acc[i][j][3])
                        : "r"(a[i][0]), "r"(a[i][1]), "r"(a[i][2]), "r"(a[i][3]),
                          "r"(b[j][0]), "r"(b[j][1]));
        }
        __syncthreads();
    }

    // epilogue: bf16 stores. (c0,c1)@(gr0,col), (c2,c3)@(gr0+8,col)
#pragma unroll
    for (int i = 0; i < 2; i++) {
        int gr0 = bm + wm * 32 + i * 16 + (lane >> 2);
        int gr1 = gr0 + 8;
        bool v0 = gr0 < M, v1 = gr1 < M;
#pragma unroll
        for (int j = 0; j < 8; j++) {
            int col = wn * 64 + j * 8 + 2 * (lane & 3);
            if (v0) {
                __nv_bfloat162 p = __float22bfloat162_rn(make_float2(acc[i][j][0], acc[i][j][1]));
                *(__nv_bfloat162*)&g_h1b[(size_t)gr0 * C1 + col] = p;
            }
            if (v1) {
                __nv_bfloat162 p = __float22bfloat162_rn(make_float2(acc[i][j][2], acc[i][j][3]));
                *(__nv_bfloat162*)&g_h1b[(size_t)gr1 * C1 + col] = p;
            }
        }
    }
}

// ---------------------------------------------------------------------------
// Fused layer-1 aggregation + ReLU + bias + GEMM2 (256->2).
// Warp per node; one LDG.128 per lane covers the full bf16 row (8 cols/lane).
__global__ __launch_bounds__(256)
void k_agg1h2(const float* __restrict__ b1, const float* __restrict__ W2, int N) {
    int node = (blockIdx.x * blockDim.x + threadIdx.x) >> 5;
    int lane = threadIdx.x & 31;
    if (node >= N) return;

    float dn = g_dinv[node];
    float self = dn * dn;

    // lane owns cols [8*lane, 8*lane+8)
    const uint4* hrow = (const uint4*)&g_h1b[(size_t)node * C1];
    float2 acc[4], bcc[4];
    {
        uint4 u = __ldg(&hrow[lane]);
        const __nv_bfloat162* p = (const __nv_bfloat162*)&u;
#pragma unroll
        for (int k = 0; k < 4; k++) {
            float2 v = __bfloat1622float2(p[k]);
            acc[k] = make_float2(v.x * self, v.y * self);
            bcc[k] = make_float2(0.f, 0.f);
        }
    }

    int beg = g_off[node];
    int end = g_off[node + 1];
    int e = beg;
    for (; e + 1 < end; e += 2) {
        int s0 = __ldg(&g_csr[e]);
        int s1 = __ldg(&g_csr[e + 1]);
        float n0 = __ldg(&g_dinv[s0]) * dn;
        float n1 = __ldg(&g_dinv[s1]) * dn;
        uint4 u0 = __ldg((const uint4*)&g_h1b[(size_t)s0 * C1] + lane);
        uint4 u1 = __ldg((const uint4*)&g_h1b[(size_t)s1 * C1] + lane);
        const __nv_bfloat162* p0 = (const __nv_bfloat162*)&u0;
        const __nv_bfloat162* p1 = (const __nv_bfloat162*)&u1;
#pragma unroll
        for (int k = 0; k < 4; k++) {
            float2 v0 = __bfloat1622float2(p0[k]);
            float2 v1 = __bfloat1622float2(p1[k]);
            acc[k].x = fmaf(v0.x, n0, acc[k].x);
            acc[k].y = fmaf(v0.y, n0, acc[k].y);
            bcc[k].x = fmaf(v1.x, n1, bcc[k].x);
            bcc[k].y = fmaf(v1.y, n1, bcc[k].y);
        }
    }
    if (e < end) {
        int s0 = __ldg(&g_csr[e]);
        float n0 = __ldg(&g_dinv[s0]) * dn;
        uint4 u0 = __ldg((const uint4*)&g_h1b[(size_t)s0 * C1] + lane);
        const __nv_bfloat162* p0 = (const __nv_bfloat162*)&u0;
#pragma unroll
        for (int k = 0; k < 4; k++) {
            float2 v0 = __bfloat1622float2(p0[k]);
            acc[k].x = fmaf(v0.x, n0, acc[k].x);
            acc[k].y = fmaf(v0.y, n0, acc[k].y);
        }
    }
#pragma unroll
    for (int k = 0; k < 4; k++) {
        acc[k].x += bcc[k].x;
        acc[k].y += bcc[k].y;
    }

    // bias + relu + 256->2: lane covers cols 8*lane..8*lane+7
    const float4* b1v = (const float4*)b1;
    float4 bbA = __ldg(&b1v[2 * lane]);
    float4 bbB = __ldg(&b1v[2 * lane + 1]);
    float xv[8];
    xv[0] = fmaxf(acc[0].x + bbA.x, 0.f);
    xv[1] = fmaxf(acc[0].y + bbA.y, 0.f);
    xv[2] = fmaxf(acc[1].x + bbA.z, 0.f);
    xv[3] = fmaxf(acc[1].y + bbA.w, 0.f);
    xv[4] = fmaxf(acc[2].x + bbB.x, 0.f);
    xv[5] = fmaxf(acc[2].y + bbB.y, 0.f);
    xv[6] = fmaxf(acc[3].x + bbB.z, 0.f);
    xv[7] = fmaxf(acc[3].y + bbB.w, 0.f);

    const float2* w2v = (const float2*)W2;
    float d0 = 0.f, d1 = 0.f;
#pragma unroll
    for (int k = 0; k < 8; k++) {
        float2 w = __ldg(&w2v[8 * lane + k]);
        d0 = fmaf(xv[k], w.x, d0);
        d1 = fmaf(xv[k], w.y, d1);
    }

#pragma unroll
    for (int off = 16; off; off >>= 1) {
        d0 += __shfl_down_sync(0xFFFFFFFFu, d0, off);
        d1 += __shfl_down_sync(0xFFFFFFFFu, d1, off);
    }
    if (lane == 0)
        *(float2*)&g_h2[node * 2] = make_float2(d0, d1);
}

// ---------------------------------------------------------------------------
// Fused layer-2 aggregation + mean-pool accumulation. Thread per node.
__global__ __launch_bounds__(256)
void k_agg2pool(const int* __restrict__ batch, int N) {
    int n = blockIdx.x * blockDim.x + threadIdx.x;
    if (n >= N) return;
    float dn = g_dinv[n];
    float2 h = *(const float2*)&g_h2[n * 2];
    float a0 = h.x * dn * dn;
    float a1 = h.y * dn * dn;
    int beg = g_off[n], end = g_off[n + 1];
    for (int e = beg; e < end; e++) {
        int s = __ldg(&g_csr[e]);
        float norm = __ldg(&g_dinv[s]) * dn;
        float2 hs = *(const float2*)&g_h2[s * 2];
        a0 = fmaf(hs.x, norm, a0);
        a1 = fmaf(hs.y, norm, a1);
    }
    int g = __ldg(&batch[n]);
    atomicAdd(&g_gsum[g * 2 + 0], a0);
    atomicAdd(&g_gsum[g * 2 + 1], a1);
    atomicAdd(&g_gcnt[g], 1.0f);
}

__global__ void k_final(const float* __restrict__ b2, float* __restrict__ out) {
    int g = blockIdx.x * blockDim.x + threadIdx.x;
    if (g >= N_GRAPHS) return;
    float c = fmaxf(g_gcnt[g], 1.0f);
    out[g * 2 + 0] = g_gsum[g * 2 + 0] / c + b2[0];
    out[g * 2 + 1] = g_gsum[g * 2 + 1] / c + b2[1];
}

// ---------------------------------------------------------------------------
extern "C" void kernel_launch(void* const* d_in, const int* in_sizes, int n_in,
                              void* d_out, int out_size) {
    const float* x     = (const float*)d_in[0];
    const int*   ei    = (const int*)d_in[1];
    const int*   batch = (const int*)d_in[2];
    const float* W1    = (const float*)d_in[3];
    const float* b1    = (const float*)d_in[4];
    const float* W2    = (const float*)d_in[5];
    const float* b2    = (const float*)d_in[6];
    float* out = (float*)d_out;

    int N = in_sizes[0] / K_DIM;     // 100000
    int E = in_sizes[1] / 2;         // 1600000
    const int* src = ei;
    const int* dst = ei + E;

    int NB = (N + 1023) / 1024;

    k_init<<<(N + 255) / 256, 256>>>(N);
    k_hist<<<(E + 255) / 256, 256>>>(dst, E);
    k_dinv<<<(N + 255) / 256, 256>>>(N);

    // CSR build
    k_bsum<<<NB, 256>>>(N);
    k_top<<<1, 32>>>(NB, N);
    k_scan<<<NB, 256>>>(N);
    k_place<<<(E + 255) / 256, 256>>>(src, dst, E);

    // layer 1 GEMM (X read once, bf16 h1 out)
    k_gemm1<<<(N + BM - 1) / BM, 512>>>(x, W1, N);

    // fused aggregation + relu + bias + GEMM2
    k_agg1h2<<<(int)(((long long)N * 32 + 255) / 256), 256>>>(b1, W2, N);

    // fused layer-2 aggregation + pooling
    k_agg2pool<<<(N + 255) / 256, 256>>>(batch, N);
    k_final<<<(N_GRAPHS + 255) / 256, 256>>>(b2, out);
}

// round 6
// speedup vs baseline: 1.1433x; 1.1433x over previous
#include <cuda_runtime.h>
#include <cuda_bf16.h>
#include <cstdint>

#define N_NODES 100000
#define C1 256
#define K_DIM 768
#define N_GRAPHS 512
#define MAX_EDGES 1600000

// ---- scratch (no allocations allowed) ----
__device__ float g_dinv[N_NODES];
__device__ __nv_bfloat16 g_h1b[(size_t)N_NODES * C1];   // x @ W1 (bf16 storage)
__device__ float g_h2[N_NODES * 2];
__device__ float g_gsum[N_GRAPHS * 2];
__device__ float g_gcnt[N_GRAPHS];
// CSR build
__device__ int g_cnt[N_NODES];
__device__ int g_cur[N_NODES];
__device__ int g_off[N_NODES + 1];
__device__ int g_csr[MAX_EDGES];
__device__ int g_bsum[128];
__device__ int g_boff[128];

// ---------------------------------------------------------------------------
__global__ void k_init(int N) {
    int i = blockIdx.x * blockDim.x + threadIdx.x;
    if (i < N) { g_cnt[i] = 0; g_cur[i] = 0; }
    if (i < N_GRAPHS * 2) g_gsum[i] = 0.0f;
    if (i < N_GRAPHS) g_gcnt[i] = 0.0f;
}

__global__ void k_hist(const int* __restrict__ dst, int E) {
    int e = blockIdx.x * blockDim.x + threadIdx.x;
    if (e < E) atomicAdd(&g_cnt[dst[e]], 1);
}

__global__ void k_dinv(int N) {
    int i = blockIdx.x * blockDim.x + threadIdx.x;
    if (i < N) g_dinv[i] = rsqrtf((float)g_cnt[i] + 1.0f);
}

// ---- two-level exclusive scan of g_cnt -> g_off ----------------------------
__global__ void k_bsum(int N) {
    __shared__ int sm[256];
    int b = blockIdx.x, t = threadIdx.x;
    int base = b * 1024 + t * 4;
    int s = 0;
#pragma unroll
    for (int j = 0; j < 4; j++) {
        int idx = base + j;
        if (idx < N) s += g_cnt[idx];
    }
    sm[t] = s;
    __syncthreads();
    for (int o = 128; o; o >>= 1) {
        if (t < o) sm[t] += sm[t + o];
        __syncthreads();
    }
    if (t == 0) g_bsum[b] = sm[0];
}

__global__ void k_top(int NB, int N) {
    if (threadIdx.x == 0 && blockIdx.x == 0) {
        int run = 0;
        for (int i = 0; i < NB; i++) { g_boff[i] = run; run += g_bsum[i]; }
        g_off[N] = run;
    }
}

__global__ void k_scan(int N) {
    __shared__ int warp_tot[8];
    int b = blockIdx.x, t = threadIdx.x;
    int lane = t & 31, wid = t >> 5;
    int base = b * 1024 + t * 4;
    int v[4];
#pragma unroll
    for (int j = 0; j < 4; j++) {
        int idx = base + j;
        v[j] = (idx < N) ? g_cnt[idx] : 0;
    }
    int tsum = v[0] + v[1] + v[2] + v[3];
    int incl = tsum;
#pragma unroll
    for (int o = 1; o < 32; o <<= 1) {
        int n = __shfl_up_sync(0xFFFFFFFFu, incl, o);
        if (lane >= o) incl += n;
    }
    if (lane == 31) warp_tot[wid] = incl;
    __syncthreads();
    if (wid == 0 && lane < 8) {
        int w = warp_tot[lane];
        int wi = w;
#pragma unroll
        for (int o = 1; o < 8; o <<= 1) {
            int n = __shfl_up_sync(0xFFu, wi, o);
            if (lane >= o) wi += n;
        }
        warp_tot[lane] = wi - w;
    }
    __syncthreads();
    int run = warp_tot[wid] + (incl - tsum) + g_boff[b];
#pragma unroll
    for (int j = 0; j < 4; j++) {
        int idx = base + j;
        if (idx < N) g_off[idx] = run;
        run += v[j];
    }
}

__global__ void k_place(const int* __restrict__ src, const int* __restrict__ dst, int E) {
    int e = blockIdx.x * blockDim.x + threadIdx.x;
    if (e >= E) return;
    int d = dst[e];
    int pos = g_off[d] + atomicAdd(&g_cur[d], 1);
    g_csr[pos] = src[e];
}

// ---------------------------------------------------------------------------
// TF32 tensor-core GEMM: h1 = X[M,768] @ W1[768,256], bf16 output.
// BM=64, BN=256 (full C1 => X read ONCE), BK=16, 256 threads, 2 CTAs/SM.
// 8 warps: wm = warp&1 (2 x 32 rows), wn = warp>>1 (4 x 64 cols).
#define BM 64
#define BN 256
#define BK 16

__global__ __launch_bounds__(256, 2)
void k_gemm1(const float* __restrict__ X, const float* __restrict__ W, int M) {
    __shared__ float As[2][BM][BK + 4];     // 10.25 KB
    __shared__ float Bs[2][BK][BN + 4];     // 33.3 KB

    const int tid  = threadIdx.x;
    const int lane = tid & 31;
    const int warp = tid >> 5;
    const int wm = warp & 1;          // 0..1 -> M offset wm*32
    const int wn = warp >> 1;         // 0..3 -> N offset wn*64
    const int bm = blockIdx.x * BM;

    float acc[2][8][4];
#pragma unroll
    for (int i = 0; i < 2; i++)
#pragma unroll
        for (int j = 0; j < 8; j++)
#pragma unroll
            for (int t = 0; t < 4; t++) acc[i][j][t] = 0.0f;

    const int NS = K_DIM / BK;  // 48

    auto load_stage = [&](int s, int buf) {
        int k0 = s * BK;
        // A tile: 64x16 = 256 float4, 1 per thread
        {
            int row = tid >> 2;
            int ch  = tid & 3;
            int gr  = bm + row;
            int sz  = (gr < M) ? 16 : 0;
            if (gr >= M) gr = M - 1;
            const float* srcp = X + (size_t)gr * K_DIM + k0 + ch * 4;
            uint32_t dstp = (uint32_t)__cvta_generic_to_shared(&As[buf][row][ch * 4]);
            asm volatile("cp.async.cg.shared.global [%0], [%1], 16, %2;\n"
                         :: "r"(dstp), "l"(srcp), "r"(sz));
        }
        // B tile: 16x256 = 1024 float4, 4 per thread
#pragma unroll
        for (int l = 0; l < 4; l++) {
            int idx = tid + l * 256;
            int row = idx >> 6;
            int ch  = idx & 63;
            const float* srcp = W + (size_t)(k0 + row) * C1 + ch * 4;
            uint32_t dstp = (uint32_t)__cvta_generic_to_shared(&Bs[buf][row][ch * 4]);
            asm volatile("cp.async.cg.shared.global [%0], [%1], 16;\n"
                         :: "r"(dstp), "l"(srcp));
        }
        asm volatile("cp.async.commit_group;\n");
    };

    load_stage(0, 0);

    for (int s = 0; s < NS; s++) {
        int buf = s & 1;
        if (s + 1 < NS) {
            load_stage(s + 1, (s + 1) & 1);
            asm volatile("cp.async.wait_group 1;\n");
        } else {
            asm volatile("cp.async.wait_group 0;\n");
        }
        __syncthreads();

#pragma unroll
        for (int kk = 0; kk < 2; kk++) {
            uint32_t a[2][4], b[8][2];
#pragma unroll
            for (int i = 0; i < 2; i++) {
                int r = wm * 32 + i * 16 + (lane >> 2);
                int c = kk * 8 + (lane & 3);
                asm("cvt.rna.tf32.f32 %0, %1;" : "=r"(a[i][0]) : "f"(As[buf][r][c]));
                asm("cvt.rna.tf32.f32 %0, %1;" : "=r"(a[i][1]) : "f"(As[buf][r + 8][c]));
                asm("cvt.rna.tf32.f32 %0, %1;" : "=r"(a[i][2]) : "f"(As[buf][r][c + 4]));
                asm("cvt.rna.tf32.f32 %0, %1;" : "=r"(a[i][3]) : "f"(As[buf][r + 8][c + 4]));
            }
#pragma unroll
            for (int j = 0; j < 8; j++) {
                int rb = kk * 8 + (lane & 3);
                int cb = wn * 64 + j * 8 + (lane >> 2);
                asm("cvt.rna.tf32.f32 %0, %1;" : "=r"(b[j][0]) : "f"(Bs[buf][rb][cb]));
                asm("cvt.rna.tf32.f32 %0, %1;" : "=r"(b[j][1]) : "f"(Bs[buf][rb + 4][cb]));
            }
#pragma unroll
            for (int i = 0; i < 2; i++)
#pragma unroll
                for (int j = 0; j < 8; j++)
                    asm volatile(
                        "mma.sync.aligned.m16n8k8.row.col.f32.tf32.tf32.f32 "
                        "{%0,%1,%2,%3}, {%4,%5,%6,%7}, {%8,%9}, {%0,%1,%2,%3};\n"
                        : "+f"(acc[i][j][0]), "+f"(acc[i][j][1]),
                          "+f"(acc[i][j][2]), "+f"(acc[i][j][3])
                        : "r"(a[i][0]), "r"(a[i][1]), "r"(a[i][2]), "r"(a[i][3]),
                          "r"(b[j][0]), "r"(b[j][1]));
        }
        __syncthreads();
    }

    // epilogue: bf16 stores. (c0,c1)@(gr0,col), (c2,c3)@(gr0+8,col)
#pragma unroll
    for (int i = 0; i < 2; i++) {
        int gr0 = bm + wm * 32 + i * 16 + (lane >> 2);
        int gr1 = gr0 + 8;
        bool v0 = gr0 < M, v1 = gr1 < M;
#pragma unroll
        for (int j = 0; j < 8; j++) {
            int col = wn * 64 + j * 8 + 2 * (lane & 3);
            if (v0) {
                __nv_bfloat162 p = __float22bfloat162_rn(make_float2(acc[i][j][0], acc[i][j][1]));
                *(__nv_bfloat162*)&g_h1b[(size_t)gr0 * C1 + col] = p;
            }
            if (v1) {
                __nv_bfloat162 p = __float22bfloat162_rn(make_float2(acc[i][j][2], acc[i][j][3]));
                *(__nv_bfloat162*)&g_h1b[(size_t)gr1 * C1 + col] = p;
            }
        }
    }
}

// ---------------------------------------------------------------------------
// Fused layer-1 aggregation + ReLU + bias + GEMM2 (256->2).
// Warp per node; one LDG.128 per lane covers the full bf16 row (8 cols/lane).
__global__ __launch_bounds__(256)
void k_agg1h2(const float* __restrict__ b1, const float* __restrict__ W2, int N) {
    int node = (blockIdx.x * blockDim.x + threadIdx.x) >> 5;
    int lane = threadIdx.x & 31;
    if (node >= N) return;

    float dn = g_dinv[node];
    float self = dn * dn;

    const uint4* hrow = (const uint4*)&g_h1b[(size_t)node * C1];
    float2 acc[4], bcc[4];
    {
        uint4 u = __ldg(&hrow[lane]);
        const __nv_bfloat162* p = (const __nv_bfloat162*)&u;
#pragma unroll
        for (int k = 0; k < 4; k++) {
            float2 v = __bfloat1622float2(p[k]);
            acc[k] = make_float2(v.x * self, v.y * self);
            bcc[k] = make_float2(0.f, 0.f);
        }
    }

    int beg = g_off[node];
    int end = g_off[node + 1];
    int e = beg;
    for (; e + 1 < end; e += 2) {
        int s0 = __ldg(&g_csr[e]);
        int s1 = __ldg(&g_csr[e + 1]);
        float n0 = __ldg(&g_dinv[s0]) * dn;
        float n1 = __ldg(&g_dinv[s1]) * dn;
        uint4 u0 = __ldg((const uint4*)&g_h1b[(size_t)s0 * C1] + lane);
        uint4 u1 = __ldg((const uint4*)&g_h1b[(size_t)s1 * C1] + lane);
        const __nv_bfloat162* p0 = (const __nv_bfloat162*)&u0;
        const __nv_bfloat162* p1 = (const __nv_bfloat162*)&u1;
#pragma unroll
        for (int k = 0; k < 4; k++) {
            float2 v0 = __bfloat1622float2(p0[k]);
            float2 v1 = __bfloat1622float2(p1[k]);
            acc[k].x = fmaf(v0.x, n0, acc[k].x);
            acc[k].y = fmaf(v0.y, n0, acc[k].y);
            bcc[k].x = fmaf(v1.x, n1, bcc[k].x);
            bcc[k].y = fmaf(v1.y, n1, bcc[k].y);
        }
    }
    if (e < end) {
        int s0 = __ldg(&g_csr[e]);
        float n0 = __ldg(&g_dinv[s0]) * dn;
        uint4 u0 = __ldg((const uint4*)&g_h1b[(size_t)s0 * C1] + lane);
        const __nv_bfloat162* p0 = (const __nv_bfloat162*)&u0;
#pragma unroll
        for (int k = 0; k < 4; k++) {
            float2 v0 = __bfloat1622float2(p0[k]);
            acc[k].x = fmaf(v0.x, n0, acc[k].x);
            acc[k].y = fmaf(v0.y, n0, acc[k].y);
        }
    }
#pragma unroll
    for (int k = 0; k < 4; k++) {
        acc[k].x += bcc[k].x;
        acc[k].y += bcc[k].y;
    }

    // bias + relu + 256->2: lane covers cols 8*lane..8*lane+7
    const float4* b1v = (const float4*)b1;
    float4 bbA = __ldg(&b1v[2 * lane]);
    float4 bbB = __ldg(&b1v[2 * lane + 1]);
    float xv[8];
    xv[0] = fmaxf(acc[0].x + bbA.x, 0.f);
    xv[1] = fmaxf(acc[0].y + bbA.y, 0.f);
    xv[2] = fmaxf(acc[1].x + bbA.z, 0.f);
    xv[3] = fmaxf(acc[1].y + bbA.w, 0.f);
    xv[4] = fmaxf(acc[2].x + bbB.x, 0.f);
    xv[5] = fmaxf(acc[2].y + bbB.y, 0.f);
    xv[6] = fmaxf(acc[3].x + bbB.z, 0.f);
    xv[7] = fmaxf(acc[3].y + bbB.w, 0.f);

    const float2* w2v = (const float2*)W2;
    float d0 = 0.f, d1 = 0.f;
#pragma unroll
    for (int k = 0; k < 8; k++) {
        float2 w = __ldg(&w2v[8 * lane + k]);
        d0 = fmaf(xv[k], w.x, d0);
        d1 = fmaf(xv[k], w.y, d1);
    }

#pragma unroll
    for (int off = 16; off; off >>= 1) {
        d0 += __shfl_down_sync(0xFFFFFFFFu, d0, off);
        d1 += __shfl_down_sync(0xFFFFFFFFu, d1, off);
    }
    if (lane == 0)
        *(float2*)&g_h2[node * 2] = make_float2(d0, d1);
}

// ---------------------------------------------------------------------------
// Fused layer-2 aggregation + mean-pool accumulation. Thread per node.
__global__ __launch_bounds__(256)
void k_agg2pool(const int* __restrict__ batch, int N) {
    int n = blockIdx.x * blockDim.x + threadIdx.x;
    if (n >= N) return;
    float dn = g_dinv[n];
    float2 h = *(const float2*)&g_h2[n * 2];
    float a0 = h.x * dn * dn;
    float a1 = h.y * dn * dn;
    int beg = g_off[n], end = g_off[n + 1];
    for (int e = beg; e < end; e++) {
        int s = __ldg(&g_csr[e]);
        float norm = __ldg(&g_dinv[s]) * dn;
        float2 hs = *(const float2*)&g_h2[s * 2];
        a0 = fmaf(hs.x, norm, a0);
        a1 = fmaf(hs.y, norm, a1);
    }
    int g = __ldg(&batch[n]);
    atomicAdd(&g_gsum[g * 2 + 0], a0);
    atomicAdd(&g_gsum[g * 2 + 1], a1);
    atomicAdd(&g_gcnt[g], 1.0f);
}

__global__ void k_final(const float* __restrict__ b2, float* __restrict__ out) {
    int g = blockIdx.x * blockDim.x + threadIdx.x;
    if (g >= N_GRAPHS) return;
    float c = fmaxf(g_gcnt[g], 1.0f);
    out[g * 2 + 0] = g_gsum[g * 2 + 0] / c + b2[0];
    out[g * 2 + 1] = g_gsum[g * 2 + 1] / c + b2[1];
}

// ---------------------------------------------------------------------------
extern "C" void kernel_launch(void* const* d_in, const int* in_sizes, int n_in,
                              void* d_out, int out_size) {
    const float* x     = (const float*)d_in[0];
    const int*   ei    = (const int*)d_in[1];
    const int*   batch = (const int*)d_in[2];
    const float* W1    = (const float*)d_in[3];
    const float* b1    = (const float*)d_in[4];
    const float* W2    = (const float*)d_in[5];
    const float* b2    = (const float*)d_in[6];
    float* out = (float*)d_out;

    int N = in_sizes[0] / K_DIM;     // 100000
    int E = in_sizes[1] / 2;         // 1600000
    const int* src = ei;
    const int* dst = ei + E;

    int NB = (N + 1023) / 1024;

    k_init<<<(N + 255) / 256, 256>>>(N);
    k_hist<<<(E + 255) / 256, 256>>>(dst, E);
    k_dinv<<<(N + 255) / 256, 256>>>(N);

    // CSR build
    k_bsum<<<NB, 256>>>(N);
    k_top<<<1, 32>>>(NB, N);
    k_scan<<<NB, 256>>>(N);
    k_place<<<(E + 255) / 256, 256>>>(src, dst, E);

    // layer 1 GEMM (X read once, bf16 h1 out, 2 CTAs/SM)
    k_gemm1<<<(N + BM - 1) / BM, 256>>>(x, W1, N);

    // fused aggregation + relu + bias + GEMM2
    k_agg1h2<<<(int)(((long long)N * 32 + 255) / 256), 256>>>(b1, W2, N);

    // fused layer-2 aggregation + pooling
    k_agg2pool<<<(N + 255) / 256, 256>>>(batch, N);
    k_final<<<(N_GRAPHS + 255) / 256, 256>>>(b2, out);
}

// round 8
// speedup vs baseline: 1.7117x; 1.4972x over previous
#include <cuda_runtime.h>
#include <cuda_bf16.h>
#include <cstdint>

#define N_NODES 100000
#define C1 256
#define K_DIM 768
#define N_GRAPHS 512
#define MAX_EDGES 1600000

// ---- scratch (no allocations allowed) ----
__device__ float g_dinv[N_NODES];
__device__ __nv_bfloat16 g_h1b[(size_t)N_NODES * C1];   // x @ W1 (bf16 storage)
__device__ __nv_bfloat16 g_w1b[K_DIM * C1];             // W1 in bf16
__device__ float g_h2[N_NODES * 2];
__device__ float g_gsum[N_GRAPHS * 2];
__device__ float g_gcnt[N_GRAPHS];
// CSR build
__device__ int g_cnt[N_NODES];
__device__ int g_cur[N_NODES];
__device__ int g_off[N_NODES + 1];
__device__ int g_csr[MAX_EDGES];
__device__ int g_bsum[128];
__device__ int g_boff[128];

// ---------------------------------------------------------------------------
__global__ void k_init(int N) {
    int i = blockIdx.x * blockDim.x + threadIdx.x;
    if (i < N) { g_cnt[i] = 0; g_cur[i] = 0; }
    if (i < N_GRAPHS * 2) g_gsum[i] = 0.0f;
    if (i < N_GRAPHS) g_gcnt[i] = 0.0f;
}

__global__ void k_wconv(const float* __restrict__ W) {
    int i = blockIdx.x * blockDim.x + threadIdx.x;   // 0 .. 98303 (x2 floats)
    if (i < K_DIM * C1 / 2) {
        float2 v = *(const float2*)&W[i * 2];
        *(__nv_bfloat162*)&g_w1b[i * 2] = __float22bfloat162_rn(v);
    }
}

__global__ void k_hist(const int* __restrict__ dst, int E) {
    int e = blockIdx.x * blockDim.x + threadIdx.x;
    if (e < E) atomicAdd(&g_cnt[dst[e]], 1);
}

__global__ void k_dinv(int N) {
    int i = blockIdx.x * blockDim.x + threadIdx.x;
    if (i < N) g_dinv[i] = rsqrtf((float)g_cnt[i] + 1.0f);
}

// ---- two-level exclusive scan of g_cnt -> g_off ----------------------------
__global__ void k_bsum(int N) {
    __shared__ int sm[256];
    int b = blockIdx.x, t = threadIdx.x;
    int base = b * 1024 + t * 4;
    int s = 0;
#pragma unroll
    for (int j = 0; j < 4; j++) {
        int idx = base + j;
        if (idx < N) s += g_cnt[idx];
    }
    sm[t] = s;
    __syncthreads();
    for (int o = 128; o; o >>= 1) {
        if (t < o) sm[t] += sm[t + o];
        __syncthreads();
    }
    if (t == 0) g_bsum[b] = sm[0];
}

__global__ void k_top(int NB, int N) {
    if (threadIdx.x == 0 && blockIdx.x == 0) {
        int run = 0;
        for (int i = 0; i < NB; i++) { g_boff[i] = run; run += g_bsum[i]; }
        g_off[N] = run;
    }
}

__global__ void k_scan(int N) {
    __shared__ int warp_tot[8];
    int b = blockIdx.x, t = threadIdx.x;
    int lane = t & 31, wid = t >> 5;
    int base = b * 1024 + t * 4;
    int v[4];
#pragma unroll
    for (int j = 0; j < 4; j++) {
        int idx = base + j;
        v[j] = (idx < N) ? g_cnt[idx] : 0;
    }
    int tsum = v[0] + v[1] + v[2] + v[3];
    int incl = tsum;
#pragma unroll
    for (int o = 1; o < 32; o <<= 1) {
        int n = __shfl_up_sync(0xFFFFFFFFu, incl, o);
        if (lane >= o) incl += n;
    }
    if (lane == 31) warp_tot[wid] = incl;
    __syncthreads();
    if (wid == 0 && lane < 8) {
        int w = warp_tot[lane];
        int wi = w;
#pragma unroll
        for (int o = 1; o < 8; o <<= 1) {
            int n = __shfl_up_sync(0xFFu, wi, o);
            if (lane >= o) wi += n;
        }
        warp_tot[lane] = wi - w;
    }
    __syncthreads();
    int run = warp_tot[wid] + (incl - tsum) + g_boff[b];
#pragma unroll
    for (int j = 0; j < 4; j++) {
        int idx = base + j;
        if (idx < N) g_off[idx] = run;
        run += v[j];
    }
}

__global__ void k_place(const int* __restrict__ src, const int* __restrict__ dst, int E) {
    int e = blockIdx.x * blockDim.x + threadIdx.x;
    if (e >= E) return;
    int d = dst[e];
    int pos = g_off[d] + atomicAdd(&g_cur[d], 1);
    g_csr[pos] = src[e];
}

// ---------------------------------------------------------------------------
// bf16 tensor-core GEMM: h1 = X[M,768] @ W1[768,256], bf16 in/out, fp32 acc.
// BM=64, BN=256 (full C1, X read once), BK=32, 256 threads, 2 CTAs/SM.
// 8 warps: wm = warp&1 (2 x 32 rows), wn = warp>>1 (4 x 64 cols).
// A: fp32->bf16 converted on the fly (LDG+cvt+STS), stride 40 bf16 (80B).
// B: bf16 via cp.async, 512B rows, XOR-16B swizzle keyed on (k&7).
#define BM 64
#define BN 256
#define BK 32

#define A_STRIDE 40                       // bf16 elements per A row
#define A_STAGE_BYTES (BM * A_STRIDE * 2) // 5120
#define B_STAGE_BYTES (BK * BN * 2)       // 16384

__global__ __launch_bounds__(256, 2)
void k_gemm1(const float* __restrict__ X, int M) {
    __shared__ __align__(16) __nv_bfloat16 As[2][BM * A_STRIDE];
    __shared__ __align__(16) char Bs[2][B_STAGE_BYTES];

    const int tid  = threadIdx.x;
    const int lane = tid & 31;
    const int warp = tid >> 5;
    const int wm = warp & 1;
    const int wn = warp >> 1;
    const int bm = blockIdx.x * BM;

    float acc[2][8][4];
#pragma unroll
    for (int i = 0; i < 2; i++)
#pragma unroll
        for (int j = 0; j < 8; j++)
#pragma unroll
            for (int t = 0; t < 4; t++) acc[i][j][t] = 0.0f;

    const int NS = K_DIM / BK;  // 24

    // ---- per-thread load geometry ----
    const int arow = tid >> 2;            // 0..63
    const int akch = tid & 3;             // 8-float chunk within BK=32
    int gr = bm + arow;
    if (gr >= M) gr = M - 1;              // clamp (masked at store)
    const float* aptr_base = X + (size_t)gr * K_DIM + akch * 8;
    uint32_t a_sts = (uint32_t)__cvta_generic_to_shared(&As[0][arow * A_STRIDE + akch * 8]);

    uint32_t bs_base = (uint32_t)__cvta_generic_to_shared(&Bs[0][0]);

    // ---- ldmatrix lane addresses (buffer 0; buffer 1 adds stage bytes) ----
    uint32_t as_l = (uint32_t)__cvta_generic_to_shared(&As[0][0])
                  + (uint32_t)((wm * 32 + (lane & 7) + 8 * ((lane >> 3) & 1)) * A_STRIDE * 2)
                  + ((lane >> 4) & 1) * 16;
    uint32_t b_krow = (lane & 7) + 8 * ((lane >> 3) & 1);
    uint32_t b_swz  = (uint32_t)(lane & 7) << 4;
    uint32_t b_col0 = (uint32_t)((wn * 64 + ((lane >> 4) & 1) * 8) * 2);

    // ---- A prefetch regs ----
    float4 a4lo, a4hi;
    auto lda = [&](int s) {
        const float* p = aptr_base + s * BK;
        a4lo = *(const float4*)p;
        a4hi = *(const float4*)(p + 4);
    };
    auto stsa = [&](int buf) {
        __nv_bfloat162 p0 = __float22bfloat162_rn(make_float2(a4lo.x, a4lo.y));
        __nv_bfloat162 p1 = __float22bfloat162_rn(make_float2(a4lo.z, a4lo.w));
        __nv_bfloat162 p2 = __float22bfloat162_rn(make_float2(a4hi.x, a4hi.y));
        __nv_bfloat162 p3 = __float22bfloat162_rn(make_float2(a4hi.z, a4hi.w));
        uint32_t u0 = *(uint32_t*)&p0, u1 = *(uint32_t*)&p1;
        uint32_t u2 = *(uint32_t*)&p2, u3 = *(uint32_t*)&p3;
        asm volatile("st.shared.v4.b32 [%0], {%1,%2,%3,%4};\n"
                     :: "r"(a_sts + buf * A_STAGE_BYTES), "r"(u0), "r"(u1), "r"(u2), "r"(u3));
    };
    auto ldb = [&](int s, int buf) {
        int k0 = s * BK;
#pragma unroll
        for (int l = 0; l < 4; l++) {
            int idx = tid + l * 256;           // 0..1023
            int row = idx >> 5;                // 0..31
            int c16 = idx & 31;
            uint32_t dcol = (uint32_t)(c16 * 16) ^ ((uint32_t)(row & 7) << 4);
            uint32_t dstp = bs_base + buf * B_STAGE_BYTES + row * 512 + dcol;
            const __nv_bfloat16* srcp = g_w1b + (size_t)(k0 + row) * C1 + c16 * 8;
            asm volatile("cp.async.cg.shared.global [%0], [%1], 16;\n"
                         :: "r"(dstp), "l"(srcp));
        }
        asm volatile("cp.async.commit_group;\n");
    };

    // prologue
    lda(0);
    ldb(0, 0);
    stsa(0);

    for (int s = 0; s < NS; s++) {
        int buf = s & 1;
        if (s + 1 < NS) {
            lda(s + 1);
            ldb(s + 1, buf ^ 1);
            asm volatile("cp.async.wait_group 1;\n");
        } else {
            asm volatile("cp.async.wait_group 0;\n");
        }
        __syncthreads();

        uint32_t a_ad = as_l + buf * A_STAGE_BYTES;
        uint32_t b_base = bs_base + buf * B_STAGE_BYTES;

#pragma unroll
        for (int ks = 0; ks < 2; ks++) {
            uint32_t a[2][4];
#pragma unroll
            for (int i = 0; i < 2; i++) {
                uint32_t ad = a_ad + i * (16 * A_STRIDE * 2) + ks * 32;
                asm volatile("ldmatrix.sync.aligned.m8n8.x4.shared.b16 {%0,%1,%2,%3}, [%4];\n"
                             : "=r"(a[i][0]), "=r"(a[i][1]), "=r"(a[i][2]), "=r"(a[i][3])
                             : "r"(ad));
            }
            uint32_t b[8][2];
#pragma unroll
            for (int jp = 0; jp < 2; jp++) {
                uint32_t ad = b_base + (ks * 16 + b_krow) * 512
                            + ((b_col0 + jp * 32) ^ b_swz);
                uint32_t r0, r1, r2, r3;
                asm volatile("ldmatrix.sync.aligned.m8n8.x4.trans.shared.b16 {%0,%1,%2,%3}, [%4];\n"
                             : "=r"(r0), "=r"(r1), "=r"(r2), "=r"(r3)
                             : "r"(ad));
                b[jp * 2 + 0][0] = r0; b[jp * 2 + 0][1] = r1;
                b[jp * 2 + 1][0] = r2; b[jp * 2 + 1][1] = r3;
            }
            // n-tiles 4..7 come from col0 + 64 bytes (n += 32)
#pragma unroll
            for (int jp = 0; jp < 2; jp++) {
                uint32_t ad = b_base + (ks * 16 + b_krow) * 512
                            + ((b_col0 + 64 + jp * 32) ^ b_swz);
                uint32_t r0, r1, r2, r3;
                asm volatile("ldmatrix.sync.aligned.m8n8.x4.trans.shared.b16 {%0,%1,%2,%3}, [%4];\n"
                             : "=r"(r0), "=r"(r1), "=r"(r2), "=r"(r3)
                             : "r"(ad));
                b[4 + jp * 2 + 0][0] = r0; b[4 + jp * 2 + 0][1] = r1;
                b[4 + jp * 2 + 1][0] = r2; b[4 + jp * 2 + 1][1] = r3;
            }
#pragma unroll
            for (int i = 0; i < 2; i++)
#pragma unroll
                for (int j = 0; j < 8; j++)
                    asm volatile(
                        "mma.sync.aligned.m16n8k16.row.col.f32.bf16.bf16.f32 "
                        "{%0,%1,%2,%3}, {%4,%5,%6,%7}, {%8,%9}, {%0,%1,%2,%3};\n"
                        : "+f"(acc[i][j][0]), "+f"(acc[i][j][1]),
                          "+f"(acc[i][j][2]), "+f"(acc[i][j][3])
                        : "r"(a[i][0]), "r"(a[i][1]), "r"(a[i][2]), "r"(a[i][3]),
                          "r"(b[j][0]), "r"(b[j][1]));
        }
        if (s + 1 < NS) stsa(buf ^ 1);
    }

    // epilogue: bf16 stores. (c0,c1)@(gr0,col), (c2,c3)@(gr0+8,col)
#pragma unroll
    for (int i = 0; i < 2; i++) {
        int gr0 = bm + wm * 32 + i * 16 + (lane >> 2);
        int gr1 = gr0 + 8;
        bool v0 = gr0 < M, v1 = gr1 < M;
#pragma unroll
        for (int j = 0; j < 8; j++) {
            int col = wn * 64 + j * 8 + 2 * (lane & 3);
            if (v0) {
                __nv_bfloat162 p = __float22bfloat162_rn(make_float2(acc[i][j][0], acc[i][j][1]));
                *(__nv_bfloat162*)&g_h1b[(size_t)gr0 * C1 + col] = p;
            }
            if (v1) {
                __nv_bfloat162 p = __float22bfloat162_rn(make_float2(acc[i][j][2], acc[i][j][3]));
                *(__nv_bfloat162*)&g_h1b[(size_t)gr1 * C1 + col] = p;
            }
        }
    }
}

// ---------------------------------------------------------------------------
// Fused layer-1 aggregation + ReLU + bias + GEMM2 (256->2).
// Warp per node; one LDG.128 per lane covers the full bf16 row (8 cols/lane).
__global__ __launch_bounds__(256)
void k_agg1h2(const float* __restrict__ b1, const float* __restrict__ W2, int N) {
    int node = (blockIdx.x * blockDim.x + threadIdx.x) >> 5;
    int lane = threadIdx.x & 31;
    if (node >= N) return;

    float dn = g_dinv[node];
    float self = dn * dn;

    const uint4* hrow = (const uint4*)&g_h1b[(size_t)node * C1];
    float2 acc[4], bcc[4];
    {
        uint4 u = __ldg(&hrow[lane]);
        const __nv_bfloat162* p = (const __nv_bfloat162*)&u;
#pragma unroll
        for (int k = 0; k < 4; k++) {
            float2 v = __bfloat1622float2(p[k]);
            acc[k] = make_float2(v.x * self, v.y * self);
            bcc[k] = make_float2(0.f, 0.f);
        }
    }

    int beg = g_off[node];
    int end = g_off[node + 1];
    int e = beg;
    for (; e + 1 < end; e += 2) {
        int s0 = __ldg(&g_csr[e]);
        int s1 = __ldg(&g_csr[e + 1]);
        float n0 = __ldg(&g_dinv[s0]) * dn;
        float n1 = __ldg(&g_dinv[s1]) * dn;
        uint4 u0 = __ldg((const uint4*)&g_h1b[(size_t)s0 * C1] + lane);
        uint4 u1 = __ldg((const uint4*)&g_h1b[(size_t)s1 * C1] + lane);
        const __nv_bfloat162* p0 = (const __nv_bfloat162*)&u0;
        const __nv_bfloat162* p1 = (const __nv_bfloat162*)&u1;
#pragma unroll
        for (int k = 0; k < 4; k++) {
            float2 v0 = __bfloat1622float2(p0[k]);
            float2 v1 = __bfloat1622float2(p1[k]);
            acc[k].x = fmaf(v0.x, n0, acc[k].x);
            acc[k].y = fmaf(v0.y, n0, acc[k].y);
            bcc[k].x = fmaf(v1.x, n1, bcc[k].x);
            bcc[k].y = fmaf(v1.y, n1, bcc[k].y);
        }
    }
    if (e < end) {
        int s0 = __ldg(&g_csr[e]);
        float n0 = __ldg(&g_dinv[s0]) * dn;
        uint4 u0 = __ldg((const uint4*)&g_h1b[(size_t)s0 * C1] + lane);
        const __nv_bfloat162* p0 = (const __nv_bfloat162*)&u0;
#pragma unroll
        for (int k = 0; k < 4; k++) {
            float2 v0 = __bfloat1622float2(p0[k]);
            acc[k].x = fmaf(v0.x, n0, acc[k].x);
            acc[k].y = fmaf(v0.y, n0, acc[k].y);
        }
    }
#pragma unroll
    for (int k = 0; k < 4; k++) {
        acc[k].x += bcc[k].x;
        acc[k].y += bcc[k].y;
    }

    const float4* b1v = (const float4*)b1;
    float4 bbA = __ldg(&b1v[2 * lane]);
    float4 bbB = __ldg(&b1v[2 * lane + 1]);
    float xv[8];
    xv[0] = fmaxf(acc[0].x + bbA.x, 0.f);
    xv[1] = fmaxf(acc[0].y + bbA.y, 0.f);
    xv[2] = fmaxf(acc[1].x + bbA.z, 0.f);
    xv[3] = fmaxf(acc[1].y + bbA.w, 0.f);
    xv[4] = fmaxf(acc[2].x + bbB.x, 0.f);
    xv[5] = fmaxf(acc[2].y + bbB.y, 0.f);
    xv[6] = fmaxf(acc[3].x + bbB.z, 0.f);
    xv[7] = fmaxf(acc[3].y + bbB.w, 0.f);

    const float2* w2v = (const float2*)W2;
    float d0 = 0.f, d1 = 0.f;
#pragma unroll
    for (int k = 0; k < 8; k++) {
        float2 w = __ldg(&w2v[8 * lane + k]);
        d0 = fmaf(xv[k], w.x, d0);
        d1 = fmaf(xv[k], w.y, d1);
    }

#pragma unroll
    for (int off = 16; off; off >>= 1) {
        d0 += __shfl_down_sync(0xFFFFFFFFu, d0, off);
        d1 += __shfl_down_sync(0xFFFFFFFFu, d1, off);
    }
    if (lane == 0)
        *(float2*)&g_h2[node * 2] = make_float2(d0, d1);
}

// ---------------------------------------------------------------------------
__global__ __launch_bounds__(256)
void k_agg2pool(const int* __restrict__ batch, int N) {
    int n = blockIdx.x * blockDim.x + threadIdx.x;
    if (n >= N) return;
    float dn = g_dinv[n];
    float2 h = *(const float2*)&g_h2[n * 2];
    float a0 = h.x * dn * dn;
    float a1 = h.y * dn * dn;
    int beg = g_off[n], end = g_off[n + 1];
    for (int e = beg; e < end; e++) {
        int s = __ldg(&g_csr[e]);
        float norm = __ldg(&g_dinv[s]) * dn;
        float2 hs = *(const float2*)&g_h2[s * 2];
        a0 = fmaf(hs.x, norm, a0);
        a1 = fmaf(hs.y, norm, a1);
    }
    int g = __ldg(&batch[n]);
    atomicAdd(&g_gsum[g * 2 + 0], a0);
    atomicAdd(&g_gsum[g * 2 + 1], a1);
    atomicAdd(&g_gcnt[g], 1.0f);
}

__global__ void k_final(const float* __restrict__ b2, float* __restrict__ out) {
    int g = blockIdx.x * blockDim.x + threadIdx.x;
    if (g >= N_GRAPHS) return;
    float c = fmaxf(g_gcnt[g], 1.0f);
    out[g * 2 + 0] = g_gsum[g * 2 + 0] / c + b2[0];
    out[g * 2 + 1] = g_gsum[g * 2 + 1] / c + b2[1];
}

// ---------------------------------------------------------------------------
extern "C" void kernel_launch(void* const* d_in, const int* in_sizes, int n_in,
                              void* d_out, int out_size) {
    const float* x     = (const float*)d_in[0];
    const int*   ei    = (const int*)d_in[1];
    const int*   batch = (const int*)d_in[2];
    const float* W1    = (const float*)d_in[3];
    const float* b1    = (const float*)d_in[4];
    const float* W2    = (const float*)d_in[5];
    const float* b2    = (const float*)d_in[6];
    float* out = (float*)d_out;

    int N = in_sizes[0] / K_DIM;     // 100000
    int E = in_sizes[1] / 2;         // 1600000
    const int* src = ei;
    const int* dst = ei + E;

    int NB = (N + 1023) / 1024;

    k_init<<<(N + 255) / 256, 256>>>(N);
    k_wconv<<<(K_DIM * C1 / 2 + 255) / 256, 256>>>(W1);
    k_hist<<<(E + 255) / 256, 256>>>(dst, E);
    k_dinv<<<(N + 255) / 256, 256>>>(N);

    // CSR build
    k_bsum<<<NB, 256>>>(N);
    k_top<<<1, 32>>>(NB, N);
    k_scan<<<NB, 256>>>(N);
    k_place<<<(E + 255) / 256, 256>>>(src, dst, E);

    // layer 1 GEMM (bf16 mma + ldmatrix, X read once, 2 CTAs/SM)
    k_gemm1<<<(N + BM - 1) / BM, 256>>>(x, N);

    // fused aggregation + relu + bias + GEMM2
    k_agg1h2<<<(int)(((long long)N * 32 + 255) / 256), 256>>>(b1, W2, N);

    // fused layer-2 aggregation + pooling
    k_agg2pool<<<(N + 255) / 256, 256>>>(batch, N);
    k_final<<<(N_GRAPHS + 255) / 256, 256>>>(b2, out);
}

// round 11
// speedup vs baseline: 1.8225x; 1.0647x over previous
#include <cuda_runtime.h>
#include <cuda_bf16.h>
#include <cstdint>

#define N_NODES 100000
#define C1 256
#define K_DIM 768
#define N_GRAPHS 512
#define MAX_EDGES 1600000

// ---- scratch (no allocations allowed) ----
__device__ float g_dinv[N_NODES];
__device__ __nv_bfloat16 g_h1b[(size_t)N_NODES * C1];   // x @ W1 (bf16 storage)
__device__ __nv_bfloat16 g_w1b[K_DIM * C1];             // W1 in bf16
__device__ float g_h2[N_NODES * 2];
__device__ float g_gsum[N_GRAPHS * 2];
__device__ float g_gcnt[N_GRAPHS];
// CSR build
__device__ int g_cnt[N_NODES];
__device__ int g_cur[N_NODES];
__device__ int g_off[N_NODES + 1];
__device__ int g_csr[MAX_EDGES];
__device__ int g_bsum[128];
__device__ int g_boff[128];

// ---- side stream + fork/join events (host resources; created at load) ----
struct SideStream {
    cudaStream_t s = nullptr;
    cudaEvent_t fork = nullptr, join = nullptr;
    SideStream() {
        cudaStreamCreateWithFlags(&s, cudaStreamNonBlocking);
        cudaEventCreateWithFlags(&fork, cudaEventDisableTiming);
        cudaEventCreateWithFlags(&join, cudaEventDisableTiming);
    }
};
static SideStream g_ss;

// ---------------------------------------------------------------------------
__global__ void k_init(int N) {
    int i = blockIdx.x * blockDim.x + threadIdx.x;
    if (i < N) { g_cnt[i] = 0; g_cur[i] = 0; }
    if (i < N_GRAPHS * 2) g_gsum[i] = 0.0f;
    if (i < N_GRAPHS) g_gcnt[i] = 0.0f;
}

__global__ void k_wconv(const float* __restrict__ W) {
    int i = blockIdx.x * blockDim.x + threadIdx.x;
    if (i < K_DIM * C1 / 2) {
        float2 v = *(const float2*)&W[i * 2];
        *(__nv_bfloat162*)&g_w1b[i * 2] = __float22bfloat162_rn(v);
    }
}

__global__ void k_hist(const int* __restrict__ dst, int E) {
    int e = blockIdx.x * blockDim.x + threadIdx.x;
    if (e < E) atomicAdd(&g_cnt[dst[e]], 1);
}

// dinv + block sums in one pass over g_cnt. grid = NB blocks of 256.
__global__ void k_dinvbsum(int N) {
    __shared__ int sm[256];
    int b = blockIdx.x, t = threadIdx.x;
    int base = b * 1024 + t * 4;
    int s = 0;
#pragma unroll
    for (int j = 0; j < 4; j++) {
        int idx = base + j;
        if (idx < N) {
            int c = g_cnt[idx];
            s += c;
            g_dinv[idx] = rsqrtf((float)c + 1.0f);
        }
    }
    sm[t] = s;
    __syncthreads();
    for (int o = 128; o; o >>= 1) {
        if (t < o) sm[t] += sm[t + o];
        __syncthreads();
    }
    if (t == 0) g_bsum[b] = sm[0];
}

__global__ void k_top(int NB, int N) {
    if (threadIdx.x == 0 && blockIdx.x == 0) {
        int run = 0;
        for (int i = 0; i < NB; i++) { g_boff[i] = run; run += g_bsum[i]; }
        g_off[N] = run;
    }
}

__global__ void k_scan(int N) {
    __shared__ int warp_tot[8];
    int b = blockIdx.x, t = threadIdx.x;
    int lane = t & 31, wid = t >> 5;
    int base = b * 1024 + t * 4;
    int v[4];
#pragma unroll
    for (int j = 0; j < 4; j++) {
        int idx = base + j;
        v[j] = (idx < N) ? g_cnt[idx] : 0;
    }
    int tsum = v[0] + v[1] + v[2] + v[3];
    int incl = tsum;
#pragma unroll
    for (int o = 1; o < 32; o <<= 1) {
        int n = __shfl_up_sync(0xFFFFFFFFu, incl, o);
        if (lane >= o) incl += n;
    }
    if (lane == 31) warp_tot[wid] = incl;
    __syncthreads();
    if (wid == 0 && lane < 8) {
        int w = warp_tot[lane];
        int wi = w;
#pragma unroll
        for (int o = 1; o < 8; o <<= 1) {
            int n = __shfl_up_sync(0xFFu, wi, o);
            if (lane >= o) wi += n;
        }
        warp_tot[lane] = wi - w;
    }
    __syncthreads();
    int run = warp_tot[wid] + (incl - tsum) + g_boff[b];
#pragma unroll
    for (int j = 0; j < 4; j++) {
        int idx = base + j;
        if (idx < N) g_off[idx] = run;
        run += v[j];
    }
}

__global__ void k_place(const int* __restrict__ src, const int* __restrict__ dst, int E) {
    int e = blockIdx.x * blockDim.x + threadIdx.x;
    if (e >= E) return;
    int d = dst[e];
    int pos = g_off[d] + atomicAdd(&g_cur[d], 1);
    g_csr[pos] = src[e];
}

// ---------------------------------------------------------------------------
// bf16 tensor-core GEMM: h1 = X[M,768] @ W1[768,256], bf16 in/out, fp32 acc.
// BM=64, BN=256 (full C1, X read once), BK=32, 256 threads, 2 CTAs/SM.
#define BM 64
#define BN 256
#define BK 32

#define A_STRIDE 40
#define A_STAGE_BYTES (BM * A_STRIDE * 2)
#define B_STAGE_BYTES (BK * BN * 2)

__global__ __launch_bounds__(256, 2)
void k_gemm1(const float* __restrict__ X, int M) {
    __shared__ __align__(16) __nv_bfloat16 As[2][BM * A_STRIDE];
    __shared__ __align__(16) char Bs[2][B_STAGE_BYTES];

    const int tid  = threadIdx.x;
    const int lane = tid & 31;
    const int warp = tid >> 5;
    const int wm = warp & 1;
    const int wn = warp >> 1;
    const int bm = blockIdx.x * BM;

    float acc[2][8][4];
#pragma unroll
    for (int i = 0; i < 2; i++)
#pragma unroll
        for (int j = 0; j < 8; j++)
#pragma unroll
            for (int t = 0; t < 4; t++) acc[i][j][t] = 0.0f;

    const int NS = K_DIM / BK;  // 24

    const int arow = tid >> 2;
    const int akch = tid & 3;
    int gr = bm + arow;
    if (gr >= M) gr = M - 1;
    const float* aptr_base = X + (size_t)gr * K_DIM + akch * 8;
    uint32_t a_sts = (uint32_t)__cvta_generic_to_shared(&As[0][arow * A_STRIDE + akch * 8]);

    uint32_t bs_base = (uint32_t)__cvta_generic_to_shared(&Bs[0][0]);

    uint32_t as_l = (uint32_t)__cvta_generic_to_shared(&As[0][0])
                  + (uint32_t)((wm * 32 + (lane & 7) + 8 * ((lane >> 3) & 1)) * A_STRIDE * 2)
                  + ((lane >> 4) & 1) * 16;
    uint32_t b_krow = (lane & 7) + 8 * ((lane >> 3) & 1);
    uint32_t b_swz  = (uint32_t)(lane & 7) << 4;
    uint32_t b_col0 = (uint32_t)((wn * 64 + ((lane >> 4) & 1) * 8) * 2);

    float4 a4lo, a4hi;
    auto lda = [&](int s) {
        const float* p = aptr_base + s * BK;
        a4lo = *(const float4*)p;
        a4hi = *(const float4*)(p + 4);
    };
    auto stsa = [&](int buf) {
        __nv_bfloat162 p0 = __float22bfloat162_rn(make_float2(a4lo.x, a4lo.y));
        __nv_bfloat162 p1 = __float22bfloat162_rn(make_float2(a4lo.z, a4lo.w));
        __nv_bfloat162 p2 = __float22bfloat162_rn(make_float2(a4hi.x, a4hi.y));
        __nv_bfloat162 p3 = __float22bfloat162_rn(make_float2(a4hi.z, a4hi.w));
        uint32_t u0 = *(uint32_t*)&p0, u1 = *(uint32_t*)&p1;
        uint32_t u2 = *(uint32_t*)&p2, u3 = *(uint32_t*)&p3;
        asm volatile("st.shared.v4.b32 [%0], {%1,%2,%3,%4};\n"
                     :: "r"(a_sts + buf * A_STAGE_BYTES), "r"(u0), "r"(u1), "r"(u2), "r"(u3));
    };
    auto ldb = [&](int s, int buf) {
        int k0 = s * BK;
#pragma unroll
        for (int l = 0; l < 4; l++) {
            int idx = tid + l * 256;
            int row = idx >> 5;
            int c16 = idx & 31;
            uint32_t dcol = (uint32_t)(c16 * 16) ^ ((uint32_t)(row & 7) << 4);
            uint32_t dstp = bs_base + buf * B_STAGE_BYTES + row * 512 + dcol;
            const __nv_bfloat16* srcp = g_w1b + (size_t)(k0 + row) * C1 + c16 * 8;
            asm volatile("cp.async.cg.shared.global [%0], [%1], 16;\n"
                         :: "r"(dstp), "l"(srcp));
        }
        asm volatile("cp.async.commit_group;\n");
    };

    lda(0);
    ldb(0, 0);
    stsa(0);

    for (int s = 0; s < NS; s++) {
        int buf = s & 1;
        if (s + 1 < NS) {
            lda(s + 1);
            ldb(s + 1, buf ^ 1);
            asm volatile("cp.async.wait_group 1;\n");
        } else {
            asm volatile("cp.async.wait_group 0;\n");
        }
        __syncthreads();

        uint32_t a_ad = as_l + buf * A_STAGE_BYTES;
        uint32_t b_base = bs_base + buf * B_STAGE_BYTES;

#pragma unroll
        for (int ks = 0; ks < 2; ks++) {
            uint32_t a[2][4];
#pragma unroll
            for (int i = 0; i < 2; i++) {
                uint32_t ad = a_ad + i * (16 * A_STRIDE * 2) + ks * 32;
                asm volatile("ldmatrix.sync.aligned.m8n8.x4.shared.b16 {%0,%1,%2,%3}, [%4];\n"
                             : "=r"(a[i][0]), "=r"(a[i][1]), "=r"(a[i][2]), "=r"(a[i][3])
                             : "r"(ad));
            }
            uint32_t b[8][2];
#pragma unroll
            for (int jp = 0; jp < 2; jp++) {
                uint32_t ad = b_base + (ks * 16 + b_krow) * 512
                            + ((b_col0 + jp * 32) ^ b_swz);
                uint32_t r0, r1, r2, r3;
                asm volatile("ldmatrix.sync.aligned.m8n8.x4.trans.shared.b16 {%0,%1,%2,%3}, [%4];\n"
                             : "=r"(r0), "=r"(r1), "=r"(r2), "=r"(r3)
                             : "r"(ad));
                b[jp * 2 + 0][0] = r0; b[jp * 2 + 0][1] = r1;
                b[jp * 2 + 1][0] = r2; b[jp * 2 + 1][1] = r3;
            }
#pragma unroll
            for (int jp = 0; jp < 2; jp++) {
                uint32_t ad = b_base + (ks * 16 + b_krow) * 512
                            + ((b_col0 + 64 + jp * 32) ^ b_swz);
                uint32_t r0, r1, r2, r3;
                asm volatile("ldmatrix.sync.aligned.m8n8.x4.trans.shared.b16 {%0,%1,%2,%3}, [%4];\n"
                             : "=r"(r0), "=r"(r1), "=r"(r2), "=r"(r3)
                             : "r"(ad));
                b[4 + jp * 2 + 0][0] = r0; b[4 + jp * 2 + 0][1] = r1;
                b[4 + jp * 2 + 1][0] = r2; b[4 + jp * 2 + 1][1] = r3;
            }
#pragma unroll
            for (int i = 0; i < 2; i++)
#pragma unroll
                for (int j = 0; j < 8; j++)
                    asm volatile(
                        "mma.sync.aligned.m16n8k16.row.col.f32.bf16.bf16.f32 "
                        "{%0,%1,%2,%3}, {%4,%5,%6,%7}, {%8,%9}, {%0,%1,%2,%3};\n"
                        : "+f"(acc[i][j][0]), "+f"(acc[i][j][1]),
                          "+f"(acc[i][j][2]), "+f"(acc[i][j][3])
                        : "r"(a[i][0]), "r"(a[i][1]), "r"(a[i][2]), "r"(a[i][3]),
                          "r"(b[j][0]), "r"(b[j][1]));
        }
        if (s + 1 < NS) stsa(buf ^ 1);
    }

#pragma unroll
    for (int i = 0; i < 2; i++) {
        int gr0 = bm + wm * 32 + i * 16 + (lane >> 2);
        int gr1 = gr0 + 8;
        bool v0 = gr0 < M, v1 = gr1 < M;
#pragma unroll
        for (int j = 0; j < 8; j++) {
            int col = wn * 64 + j * 8 + 2 * (lane & 3);
            if (v0) {
                __nv_bfloat162 p = __float22bfloat162_rn(make_float2(acc[i][j][0], acc[i][j][1]));
                *(__nv_bfloat162*)&g_h1b[(size_t)gr0 * C1 + col] = p;
            }
            if (v1) {
                __nv_bfloat162 p = __float22bfloat162_rn(make_float2(acc[i][j][2], acc[i][j][3]));
                *(__nv_bfloat162*)&g_h1b[(size_t)gr1 * C1 + col] = p;
            }
        }
    }
}

// ---------------------------------------------------------------------------
// Fused layer-1 aggregation + ReLU + bias + GEMM2 (256->2). Warp per node.
__global__ __launch_bounds__(256)
void k_agg1h2(const float* __restrict__ b1, const float* __restrict__ W2, int N) {
    int node = (blockIdx.x * blockDim.x + threadIdx.x) >> 5;
    int lane = threadIdx.x & 31;
    if (node >= N) return;

    float dn = g_dinv[node];
    float self = dn * dn;

    const uint4* hrow = (const uint4*)&g_h1b[(size_t)node * C1];
    float2 acc[4], bcc[4];
    {
        uint4 u = __ldg(&hrow[lane]);
        const __nv_bfloat162* p = (const __nv_bfloat162*)&u;
#pragma unroll
        for (int k = 0; k < 4; k++) {
            float2 v = __bfloat1622float2(p[k]);
            acc[k] = make_float2(v.x * self, v.y * self);
            bcc[k] = make_float2(0.f, 0.f);
        }
    }

    int beg = g_off[node];
    int end = g_off[node + 1];
    int e = beg;
    for (; e + 1 < end; e += 2) {
        int s0 = __ldg(&g_csr[e]);
        int s1 = __ldg(&g_csr[e + 1]);
        float n0 = __ldg(&g_dinv[s0]) * dn;
        float n1 = __ldg(&g_dinv[s1]) * dn;
        uint4 u0 = __ldg((const uint4*)&g_h1b[(size_t)s0 * C1] + lane);
        uint4 u1 = __ldg((const uint4*)&g_h1b[(size_t)s1 * C1] + lane);
        const __nv_bfloat162* p0 = (const __nv_bfloat162*)&u0;
        const __nv_bfloat162* p1 = (const __nv_bfloat162*)&u1;
#pragma unroll
        for (int k = 0; k < 4; k++) {
            float2 v0 = __bfloat1622float2(p0[k]);
            float2 v1 = __bfloat1622float2(p1[k]);
            acc[k].x = fmaf(v0.x, n0, acc[k].x);
            acc[k].y = fmaf(v0.y, n0, acc[k].y);
            bcc[k].x = fmaf(v1.x, n1, bcc[k].x);
            bcc[k].y = fmaf(v1.y, n1, bcc[k].y);
        }
    }
    if (e < end) {
        int s0 = __ldg(&g_csr[e]);
        float n0 = __ldg(&g_dinv[s0]) * dn;
        uint4 u0 = __ldg((const uint4*)&g_h1b[(size_t)s0 * C1] + lane);
        const __nv_bfloat162* p0 = (const __nv_bfloat162*)&u0;
#pragma unroll
        for (int k = 0; k < 4; k++) {
            float2 v0 = __bfloat1622float2(p0[k]);
            acc[k].x = fmaf(v0.x, n0, acc[k].x);
            acc[k].y = fmaf(v0.y, n0, acc[k].y);
        }
    }
#pragma unroll
    for (int k = 0; k < 4; k++) {
        acc[k].x += bcc[k].x;
        acc[k].y += bcc[k].y;
    }

    const float4* b1v = (const float4*)b1;
    float4 bbA = __ldg(&b1v[2 * lane]);
    float4 bbB = __ldg(&b1v[2 * lane + 1]);
    float xv[8];
    xv[0] = fmaxf(acc[0].x + bbA.x, 0.f);
    xv[1] = fmaxf(acc[0].y + bbA.y, 0.f);
    xv[2] = fmaxf(acc[1].x + bbA.z, 0.f);
    xv[3] = fmaxf(acc[1].y + bbA.w, 0.f);
    xv[4] = fmaxf(acc[2].x + bbB.x, 0.f);
    xv[5] = fmaxf(acc[2].y + bbB.y, 0.f);
    xv[6] = fmaxf(acc[3].x + bbB.z, 0.f);
    xv[7] = fmaxf(acc[3].y + bbB.w, 0.f);

    const float2* w2v = (const float2*)W2;
    float d0 = 0.f, d1 = 0.f;
#pragma unroll
    for (int k = 0; k < 8; k++) {
        float2 w = __ldg(&w2v[8 * lane + k]);
        d0 = fmaf(xv[k], w.x, d0);
        d1 = fmaf(xv[k], w.y, d1);
    }

#pragma unroll
    for (int off = 16; off; off >>= 1) {
        d0 += __shfl_down_sync(0xFFFFFFFFu, d0, off);
        d1 += __shfl_down_sync(0xFFFFFFFFu, d1, off);
    }
    if (lane == 0)
        *(float2*)&g_h2[node * 2] = make_float2(d0, d1);
}

// ---------------------------------------------------------------------------
__global__ __launch_bounds__(256)
void k_agg2pool(const int* __restrict__ batch, int N) {
    int n = blockIdx.x * blockDim.x + threadIdx.x;
    if (n >= N) return;
    float dn = g_dinv[n];
    float2 h = *(const float2*)&g_h2[n * 2];
    float a0 = h.x * dn * dn;
    float a1 = h.y * dn * dn;
    int beg = g_off[n], end = g_off[n + 1];
    for (int e = beg; e < end; e++) {
        int s = __ldg(&g_csr[e]);
        float norm = __ldg(&g_dinv[s]) * dn;
        float2 hs = *(const float2*)&g_h2[s * 2];
        a0 = fmaf(hs.x, norm, a0);
        a1 = fmaf(hs.y, norm, a1);
    }
    int g = __ldg(&batch[n]);
    atomicAdd(&g_gsum[g * 2 + 0], a0);
    atomicAdd(&g_gsum[g * 2 + 1], a1);
    atomicAdd(&g_gcnt[g], 1.0f);
}

__global__ void k_final(const float* __restrict__ b2, float* __restrict__ out) {
    int g = blockIdx.x * blockDim.x + threadIdx.x;
    if (g >= N_GRAPHS) return;
    float c = fmaxf(g_gcnt[g], 1.0f);
    out[g * 2 + 0] = g_gsum[g * 2 + 0] / c + b2[0];
    out[g * 2 + 1] = g_gsum[g * 2 + 1] / c + b2[1];
}

// ---------------------------------------------------------------------------
extern "C" void kernel_launch(void* const* d_in, const int* in_sizes, int n_in,
                              void* d_out, int out_size) {
    const float* x     = (const float*)d_in[0];
    const int*   ei    = (const int*)d_in[1];
    const int*   batch = (const int*)d_in[2];
    const float* W1    = (const float*)d_in[3];
    const float* b1    = (const float*)d_in[4];
    const float* W2    = (const float*)d_in[5];
    const float* b2    = (const float*)d_in[6];
    float* out = (float*)d_out;

    int N = in_sizes[0] / K_DIM;     // 100000
    int E = in_sizes[1] / 2;         // 1600000
    const int* src = ei;
    const int* dst = ei + E;

    int NB = (N + 1023) / 1024;
    cudaStream_t s2 = g_ss.s;

    // ---- fork: CSR chain on s2, wconv+gemm1 on main stream ----
    cudaEventRecord(g_ss.fork, 0);
    cudaStreamWaitEvent(s2, g_ss.fork, 0);

    // branch B (s2): CSR build
    k_init<<<(N + 255) / 256, 256, 0, s2>>>(N);
    k_hist<<<(E + 255) / 256, 256, 0, s2>>>(dst, E);
    k_dinvbsum<<<NB, 256, 0, s2>>>(N);
    k_top<<<1, 32, 0, s2>>>(NB, N);
    k_scan<<<NB, 256, 0, s2>>>(N);
    k_place<<<(E + 255) / 256, 256, 0, s2>>>(src, dst, E);
    cudaEventRecord(g_ss.join, s2);

    // branch A (main): W1 conversion + GEMM1
    k_wconv<<<(K_DIM * C1 / 2 + 255) / 256, 256>>>(W1);
    k_gemm1<<<(N + BM - 1) / BM, 256>>>(x, N);

    // ---- join ----
    cudaStreamWaitEvent(0, g_ss.join, 0);

    // fused aggregation + relu + bias + GEMM2
    k_agg1h2<<<(int)(((long long)N * 32 + 255) / 256), 256>>>(b1, W2, N);

    // fused layer-2 aggregation + pooling
    k_agg2pool<<<(N + 255) / 256, 256>>>(batch, N);
    k_final<<<(N_GRAPHS + 255) / 256, 256>>>(b2, out);
}